// round 6
// baseline (speedup 1.0000x reference)
#include <cuda_runtime.h>
#include <math.h>

#define T_STEPS 256
#define INPUT   12288
#define HID     1024
#define GATES   4096

// ---------------- device scratch (no allocations allowed) ----------------
__device__ float        g_xproj[T_STEPS * GATES];  // 4 MB
// hidden state: plain floats, ping-pong by t parity
__device__ float        g_hv[2][HID];
// packed per-CTA epochs: g_epoch[p][b] == t  <=>  CTA b's units for step t are in g_hv[p]
__device__ unsigned int g_epoch[2][128];

// ---------------- helpers: packed f32x2 FMA ----------------
__device__ __forceinline__ unsigned long long dup2(float x) {
    unsigned long long r;
    asm("mov.b64 %0, {%1, %1};" : "=l"(r) : "f"(x));
    return r;
}
__device__ __forceinline__ void ffma2(unsigned long long& d,
                                      unsigned long long a,
                                      unsigned long long b) {
    asm("fma.rn.f32x2 %0, %1, %2, %0;" : "+l"(d) : "l"(a), "l"(b));
}
__device__ __forceinline__ void unpack2(unsigned long long v, float& lo, float& hi) {
    asm("mov.b64 {%0, %1}, %2;" : "=f"(lo), "=f"(hi) : "l"(v));
}

// ---------------- init: h_0 = 0; buffer0 epochs valid(0), buffer1 invalid ----------------
__global__ void init_kernel() {
    int tid = blockIdx.x * blockDim.x + threadIdx.x;
    if (tid < HID) { g_hv[0][tid] = 0.f; g_hv[1][tid] = 0.f; }
    if (tid < 128) {
        g_epoch[0][tid] = 0u;
        g_epoch[1][tid] = 0xFFFFFFFFu;
    }
}

// ---------------- GEMM1: x_proj = frames @ W_ih^T + b_ih + b_hh (unchanged) ----------------
#define BM 64
#define BN 128
#define BK 32
#define NT (INPUT / BK)   // 384 k-tiles

__global__ __launch_bounds__(256, 1)
void gemm1_kernel(const float* __restrict__ A,
                  const float* __restrict__ B,
                  const float* __restrict__ b_ih,
                  const float* __restrict__ b_hh) {
    __shared__ float As[2][BK][BM];
    __shared__ float Bs[2][BK][BN];

    const int tid = threadIdx.x;
    const int ty  = tid >> 4;
    const int tx  = tid & 15;
    const int m0  = blockIdx.y * BM;
    const int n0  = blockIdx.x * BN;

    unsigned long long acc[4][4];
#pragma unroll
    for (int i = 0; i < 4; i++)
#pragma unroll
        for (int j = 0; j < 4; j++) acc[i][j] = 0ULL;

    float4 aReg[2], bReg[4];
    int mA[2], kqA[2], nB[4], kqB[4];
#pragma unroll
    for (int p = 0; p < 2; p++) {
        int idx = p * 256 + tid;
        mA[p] = idx & 63; kqA[p] = idx >> 6;
    }
#pragma unroll
    for (int p = 0; p < 4; p++) {
        int idx = p * 256 + tid;
        nB[p] = idx & 127; kqB[p] = idx >> 7;
    }

#pragma unroll
    for (int p = 0; p < 2; p++)
        aReg[p] = *(const float4*)(A + (size_t)(m0 + mA[p]) * INPUT + kqA[p] * 4);
#pragma unroll
    for (int p = 0; p < 4; p++)
        bReg[p] = *(const float4*)(B + (size_t)(n0 + nB[p]) * INPUT + kqB[p] * 4);
#pragma unroll
    for (int p = 0; p < 2; p++) {
        As[0][kqA[p] * 4 + 0][mA[p]] = aReg[p].x;
        As[0][kqA[p] * 4 + 1][mA[p]] = aReg[p].y;
        As[0][kqA[p] * 4 + 2][mA[p]] = aReg[p].z;
        As[0][kqA[p] * 4 + 3][mA[p]] = aReg[p].w;
    }
#pragma unroll
    for (int p = 0; p < 4; p++) {
        Bs[0][kqB[p] * 4 + 0][nB[p]] = bReg[p].x;
        Bs[0][kqB[p] * 4 + 1][nB[p]] = bReg[p].y;
        Bs[0][kqB[p] * 4 + 2][nB[p]] = bReg[p].z;
        Bs[0][kqB[p] * 4 + 3][nB[p]] = bReg[p].w;
    }
    __syncthreads();

    int buf = 0;
    for (int kt = 0; kt < NT; kt++) {
        if (kt + 1 < NT) {
            int kbase = (kt + 1) * BK;
#pragma unroll
            for (int p = 0; p < 2; p++)
                aReg[p] = *(const float4*)(A + (size_t)(m0 + mA[p]) * INPUT + kbase + kqA[p] * 4);
#pragma unroll
            for (int p = 0; p < 4; p++)
                bReg[p] = *(const float4*)(B + (size_t)(n0 + nB[p]) * INPUT + kbase + kqB[p] * 4);
        }
#pragma unroll
        for (int kk = 0; kk < BK; kk++) {
            float4 a4 = *(const float4*)&As[buf][kk][ty * 4];
            unsigned long long av[4];
            av[0] = dup2(a4.x); av[1] = dup2(a4.y);
            av[2] = dup2(a4.z); av[3] = dup2(a4.w);
            ulonglong2 bv0 = *(const ulonglong2*)&Bs[buf][kk][tx * 4];
            ulonglong2 bv1 = *(const ulonglong2*)&Bs[buf][kk][64 + tx * 4];
#pragma unroll
            for (int i = 0; i < 4; i++) {
                ffma2(acc[i][0], av[i], bv0.x);
                ffma2(acc[i][1], av[i], bv0.y);
                ffma2(acc[i][2], av[i], bv1.x);
                ffma2(acc[i][3], av[i], bv1.y);
            }
        }
        if (kt + 1 < NT) {
            int nb = buf ^ 1;
#pragma unroll
            for (int p = 0; p < 2; p++) {
                As[nb][kqA[p] * 4 + 0][mA[p]] = aReg[p].x;
                As[nb][kqA[p] * 4 + 1][mA[p]] = aReg[p].y;
                As[nb][kqA[p] * 4 + 2][mA[p]] = aReg[p].z;
                As[nb][kqA[p] * 4 + 3][mA[p]] = aReg[p].w;
            }
#pragma unroll
            for (int p = 0; p < 4; p++) {
                Bs[nb][kqB[p] * 4 + 0][nB[p]] = bReg[p].x;
                Bs[nb][kqB[p] * 4 + 1][nB[p]] = bReg[p].y;
                Bs[nb][kqB[p] * 4 + 2][nB[p]] = bReg[p].z;
                Bs[nb][kqB[p] * 4 + 3][nB[p]] = bReg[p].w;
            }
            __syncthreads();
            buf = nb;
        }
    }

    const int n1 = n0 + tx * 4;
    const int n2 = n0 + 64 + tx * 4;
    float4 bi1 = *(const float4*)&b_ih[n1];
    float4 bh1 = *(const float4*)&b_hh[n1];
    float4 bi2 = *(const float4*)&b_ih[n2];
    float4 bh2 = *(const float4*)&b_hh[n2];
#pragma unroll
    for (int i = 0; i < 4; i++) {
        int m = m0 + ty * 4 + i;
        float* crow = g_xproj + (size_t)m * GATES;
        float l0, h0, l1, h1;
        unpack2(acc[i][0], l0, h0);
        unpack2(acc[i][1], l1, h1);
        float4 v1 = make_float4(l0 + bi1.x + bh1.x, h0 + bi1.y + bh1.y,
                                l1 + bi1.z + bh1.z, h1 + bi1.w + bh1.w);
        *(float4*)&crow[n1] = v1;
        unpack2(acc[i][2], l0, h0);
        unpack2(acc[i][3], l1, h1);
        float4 v2 = make_float4(l0 + bi2.x + bh2.x, h0 + bi2.y + bh2.y,
                                l1 + bi2.z + bh2.z, h1 + bi2.w + bh2.w);
        *(float4*)&crow[n2] = v2;
    }
}

// ---------------- persistent LSTM scan: packed-epoch sync, warp-0 poll ----------------
#define SCAN_CTAS 128

__device__ __forceinline__ float fast_sigmoid(float x) {
    return __fdividef(1.f, 1.f + __expf(-x));
}
__device__ __forceinline__ float fast_tanh(float x) {
    float e = __expf(-2.f * x);
    return __fdividef(1.f - e, 1.f + e);
}
__device__ __forceinline__ unsigned long long ld_rlx64(const unsigned long long* p) {
    unsigned long long v;
    asm volatile("ld.relaxed.gpu.global.u64 %0, [%1];" : "=l"(v) : "l"(p) : "memory");
    return v;
}
__device__ __forceinline__ void st_rlx32f(float* p, float v) {
    asm volatile("st.relaxed.gpu.global.f32 [%0], %1;" :: "l"(p), "f"(v) : "memory");
}
__device__ __forceinline__ void st_rlx32u(unsigned int* p, unsigned int v) {
    asm volatile("st.relaxed.gpu.global.u32 [%0], %1;" :: "l"(p), "r"(v) : "memory");
}

__global__ __launch_bounds__(256, 1)
void scan_kernel(const float* __restrict__ Whh) {
    __shared__ float hs[HID];

    const int tid  = threadIdx.x;
    const int warp = tid >> 5;
    const int lane = tid & 31;
    const int b    = blockIdx.x;
    const int j    = b * 8 + warp;   // this warp's hidden unit

    // W fragment in registers: gate g, chunk i -> floats [lane*4 + i*128, +4)
    unsigned long long wreg[4][8][2];
#pragma unroll
    for (int g = 0; g < 4; g++) {
        const float* wrow = Whh + (size_t)(g * HID + j) * HID;
#pragma unroll
        for (int i = 0; i < 8; i++) {
            ulonglong2 v = *(const ulonglong2*)&wrow[lane * 4 + i * 128];
            wreg[g][i][0] = v.x;
            wreg[g][i][1] = v.y;
        }
    }

    float cstate = 0.f;

    for (int t = 0; t < T_STEPS; t++) {
        // prefetch this step's x_proj gates (independent of h)
        float xg0 = __ldg(&g_xproj[(size_t)t * GATES + 0 * HID + j]);
        float xg1 = __ldg(&g_xproj[(size_t)t * GATES + 1 * HID + j]);
        float xg2 = __ldg(&g_xproj[(size_t)t * GATES + 2 * HID + j]);
        float xg3 = __ldg(&g_xproj[(size_t)t * GATES + 3 * HID + j]);

        // ---- warp 0 polls the 128 packed epochs (2 u64 = 4 epochs per lane) ----
        if (warp == 0) {
            const unsigned long long* ep =
                (const unsigned long long*)g_epoch[t & 1] + lane * 2;
            const unsigned long long want =
                ((unsigned long long)(unsigned int)t << 32) | (unsigned int)t;
            bool ok;
            do {
                unsigned long long v0 = ld_rlx64(ep);
                unsigned long long v1 = ld_rlx64(ep + 1);
                ok = (v0 == want) & (v1 == want);
            } while (!__all_sync(0xffffffffu, ok));
            __threadfence();   // gpu-scope acquire; bar below broadcasts it
        }
        __syncthreads();

        // ---- stage h_t into smem: one coalesced LDG.128 + STS.128 per thread ----
        float4 hv = __ldcg((const float4*)(g_hv[t & 1] + tid * 4));
        *(float4*)&hs[tid * 4] = hv;
        __syncthreads();

        // ---- gate matvec (W in regs, h in smem) ----
        unsigned long long acc[4] = {0ULL, 0ULL, 0ULL, 0ULL};
#pragma unroll
        for (int i = 0; i < 8; i++) {
            ulonglong2 h2 = *(const ulonglong2*)&hs[lane * 4 + i * 128];
#pragma unroll
            for (int g = 0; g < 4; g++) {
                ffma2(acc[g], h2.x, wreg[g][i][0]);
                ffma2(acc[g], h2.y, wreg[g][i][1]);
            }
        }

        float red[4];
#pragma unroll
        for (int g = 0; g < 4; g++) {
            float lo, hi;
            unpack2(acc[g], lo, hi);
            red[g] = lo + hi;
        }
#pragma unroll
        for (int o = 16; o; o >>= 1) {
#pragma unroll
            for (int g = 0; g < 4; g++)
                red[g] += __shfl_xor_sync(0xffffffffu, red[g], o);
        }

        float gi = fast_sigmoid(xg0 + red[0]);
        float gf = fast_sigmoid(xg1 + red[1]);
        float gg = fast_tanh(xg2 + red[2]);
        float go = fast_sigmoid(xg3 + red[3]);
        cstate = gf * cstate + gi * gg;
        float hnew = go * fast_tanh(cstate);

        // ---- publish: h stores, CTA barrier, fence+epoch by one thread ----
        if (lane == 0) st_rlx32f(&g_hv[(t + 1) & 1][j], hnew);
        __syncthreads();   // all 8 units stored (also guards hs reuse next iter)
        if (tid == 0) {
            __threadfence();                       // release h stores to gpu scope
            st_rlx32u(&g_epoch[(t + 1) & 1][b], (unsigned int)(t + 1));
        }
    }
}

// ---------------- final: out = h_T @ fc_w^T + fc_b ----------------
__global__ __launch_bounds__(256, 2)
void final_kernel(const float* __restrict__ fcw,
                  const float* __restrict__ fcb,
                  float* __restrict__ out) {
    __shared__ float hs[HID];
    const int tid = threadIdx.x, warp = tid >> 5, lane = tid & 31;
    // h_T lives in g_hv[0] (t=255 publishes into buffer (255+1)&1 = 0)
    *(float4*)&hs[tid * 4] = *(const float4*)(g_hv[0] + tid * 4);
    __syncthreads();

    int row = blockIdx.x * 16 + warp * 2;
    const float* wr0 = fcw + (size_t)row * HID;
    const float* wr1 = wr0 + HID;
    float acc0 = 0.f, acc1 = 0.f;
#pragma unroll
    for (int i = 0; i < 8; i++) {
        float4 h4 = *(const float4*)&hs[lane * 4 + i * 128];
        float4 a4 = *(const float4*)&wr0[lane * 4 + i * 128];
        float4 b4 = *(const float4*)&wr1[lane * 4 + i * 128];
        acc0 += a4.x * h4.x + a4.y * h4.y + a4.z * h4.z + a4.w * h4.w;
        acc1 += b4.x * h4.x + b4.y * h4.y + b4.z * h4.z + b4.w * h4.w;
    }
#pragma unroll
    for (int o = 16; o; o >>= 1) {
        acc0 += __shfl_xor_sync(0xffffffffu, acc0, o);
        acc1 += __shfl_xor_sync(0xffffffffu, acc1, o);
    }
    if (lane == 0) {
        out[row]     = acc0 + fcb[row];
        out[row + 1] = acc1 + fcb[row + 1];
    }
}

// ---------------- launch ----------------
extern "C" void kernel_launch(void* const* d_in, const int* in_sizes, int n_in,
                              void* d_out, int out_size) {
    const float* frames = (const float*)d_in[0];
    const float* W_ih   = (const float*)d_in[1];
    const float* W_hh   = (const float*)d_in[2];
    const float* b_ih   = (const float*)d_in[3];
    const float* b_hh   = (const float*)d_in[4];
    const float* fc_w   = (const float*)d_in[5];
    const float* fc_b   = (const float*)d_in[6];
    float* out = (float*)d_out;

    init_kernel<<<4, 256>>>();

    dim3 g1(GATES / BN, T_STEPS / BM);   // (32, 4) = 128 CTAs
    gemm1_kernel<<<g1, 256>>>(frames, W_ih, b_ih, b_hh);

    scan_kernel<<<SCAN_CTAS, 256>>>(W_hh);

    final_kernel<<<12288 / 16, 256>>>(fc_w, fc_b, out);
}

// round 7
// speedup vs baseline: 1.3617x; 1.3617x over previous
#include <cuda_runtime.h>
#include <math.h>

#define T_STEPS 256
#define INPUT   12288
#define HID     1024
#define GATES   4096

// ---------------- device scratch (no allocations allowed) ----------------
__device__ float              g_xproj[T_STEPS * GATES];  // 4 MB
// hidden state published as {epoch:32 | float_bits:32}, ping-pong by t parity
__device__ unsigned long long g_hp[2][HID];

// ---------------- helpers: packed f32x2 FMA ----------------
__device__ __forceinline__ unsigned long long dup2(float x) {
    unsigned long long r;
    asm("mov.b64 %0, {%1, %1};" : "=l"(r) : "f"(x));
    return r;
}
__device__ __forceinline__ void ffma2(unsigned long long& d,
                                      unsigned long long a,
                                      unsigned long long b) {
    asm("fma.rn.f32x2 %0, %1, %2, %0;" : "+l"(d) : "l"(a), "l"(b));
}
__device__ __forceinline__ void unpack2(unsigned long long v, float& lo, float& hi) {
    asm("mov.b64 {%0, %1}, %2;" : "=f"(lo), "=f"(hi) : "l"(v));
}

// ---------------- init: h_0 = 0 with epoch 0 in both buffers ----------------
__global__ void init_kernel() {
    int tid = blockIdx.x * blockDim.x + threadIdx.x;
    if (tid < HID) {
        g_hp[0][tid] = 0ULL;   // epoch 0, h = 0.0f
        g_hp[1][tid] = 0ULL;
    }
}

// ---------------- GEMM1: x_proj = frames @ W_ih^T + b_ih + b_hh ----------------
// (identical to R5 — fma-pipe-bound, conflict-free LDS/STS)
#define BM 64
#define BN 128
#define BK 32
#define NT (INPUT / BK)   // 384 k-tiles

__global__ __launch_bounds__(256, 1)
void gemm1_kernel(const float* __restrict__ A,
                  const float* __restrict__ B,
                  const float* __restrict__ b_ih,
                  const float* __restrict__ b_hh) {
    __shared__ float As[2][BK][BM];
    __shared__ float Bs[2][BK][BN];

    const int tid = threadIdx.x;
    const int ty  = tid >> 4;
    const int tx  = tid & 15;
    const int m0  = blockIdx.y * BM;
    const int n0  = blockIdx.x * BN;

    unsigned long long acc[4][4];
#pragma unroll
    for (int i = 0; i < 4; i++)
#pragma unroll
        for (int j = 0; j < 4; j++) acc[i][j] = 0ULL;

    float4 aReg[2], bReg[4];
    int mA[2], kqA[2], nB[4], kqB[4];
#pragma unroll
    for (int p = 0; p < 2; p++) {
        int idx = p * 256 + tid;
        mA[p] = idx & 63; kqA[p] = idx >> 6;
    }
#pragma unroll
    for (int p = 0; p < 4; p++) {
        int idx = p * 256 + tid;
        nB[p] = idx & 127; kqB[p] = idx >> 7;
    }

#pragma unroll
    for (int p = 0; p < 2; p++)
        aReg[p] = *(const float4*)(A + (size_t)(m0 + mA[p]) * INPUT + kqA[p] * 4);
#pragma unroll
    for (int p = 0; p < 4; p++)
        bReg[p] = *(const float4*)(B + (size_t)(n0 + nB[p]) * INPUT + kqB[p] * 4);
#pragma unroll
    for (int p = 0; p < 2; p++) {
        As[0][kqA[p] * 4 + 0][mA[p]] = aReg[p].x;
        As[0][kqA[p] * 4 + 1][mA[p]] = aReg[p].y;
        As[0][kqA[p] * 4 + 2][mA[p]] = aReg[p].z;
        As[0][kqA[p] * 4 + 3][mA[p]] = aReg[p].w;
    }
#pragma unroll
    for (int p = 0; p < 4; p++) {
        Bs[0][kqB[p] * 4 + 0][nB[p]] = bReg[p].x;
        Bs[0][kqB[p] * 4 + 1][nB[p]] = bReg[p].y;
        Bs[0][kqB[p] * 4 + 2][nB[p]] = bReg[p].z;
        Bs[0][kqB[p] * 4 + 3][nB[p]] = bReg[p].w;
    }
    __syncthreads();

    int buf = 0;
    for (int kt = 0; kt < NT; kt++) {
        if (kt + 1 < NT) {
            int kbase = (kt + 1) * BK;
#pragma unroll
            for (int p = 0; p < 2; p++)
                aReg[p] = *(const float4*)(A + (size_t)(m0 + mA[p]) * INPUT + kbase + kqA[p] * 4);
#pragma unroll
            for (int p = 0; p < 4; p++)
                bReg[p] = *(const float4*)(B + (size_t)(n0 + nB[p]) * INPUT + kbase + kqB[p] * 4);
        }
#pragma unroll
        for (int kk = 0; kk < BK; kk++) {
            float4 a4 = *(const float4*)&As[buf][kk][ty * 4];
            unsigned long long av[4];
            av[0] = dup2(a4.x); av[1] = dup2(a4.y);
            av[2] = dup2(a4.z); av[3] = dup2(a4.w);
            ulonglong2 bv0 = *(const ulonglong2*)&Bs[buf][kk][tx * 4];
            ulonglong2 bv1 = *(const ulonglong2*)&Bs[buf][kk][64 + tx * 4];
#pragma unroll
            for (int i = 0; i < 4; i++) {
                ffma2(acc[i][0], av[i], bv0.x);
                ffma2(acc[i][1], av[i], bv0.y);
                ffma2(acc[i][2], av[i], bv1.x);
                ffma2(acc[i][3], av[i], bv1.y);
            }
        }
        if (kt + 1 < NT) {
            int nb = buf ^ 1;
#pragma unroll
            for (int p = 0; p < 2; p++) {
                As[nb][kqA[p] * 4 + 0][mA[p]] = aReg[p].x;
                As[nb][kqA[p] * 4 + 1][mA[p]] = aReg[p].y;
                As[nb][kqA[p] * 4 + 2][mA[p]] = aReg[p].z;
                As[nb][kqA[p] * 4 + 3][mA[p]] = aReg[p].w;
            }
#pragma unroll
            for (int p = 0; p < 4; p++) {
                Bs[nb][kqB[p] * 4 + 0][nB[p]] = bReg[p].x;
                Bs[nb][kqB[p] * 4 + 1][nB[p]] = bReg[p].y;
                Bs[nb][kqB[p] * 4 + 2][nB[p]] = bReg[p].z;
                Bs[nb][kqB[p] * 4 + 3][nB[p]] = bReg[p].w;
            }
            __syncthreads();
            buf = nb;
        }
    }

    const int n1 = n0 + tx * 4;
    const int n2 = n0 + 64 + tx * 4;
    float4 bi1 = *(const float4*)&b_ih[n1];
    float4 bh1 = *(const float4*)&b_hh[n1];
    float4 bi2 = *(const float4*)&b_ih[n2];
    float4 bh2 = *(const float4*)&b_hh[n2];
#pragma unroll
    for (int i = 0; i < 4; i++) {
        int m = m0 + ty * 4 + i;
        float* crow = g_xproj + (size_t)m * GATES;
        float l0, h0, l1, h1;
        unpack2(acc[i][0], l0, h0);
        unpack2(acc[i][1], l1, h1);
        float4 v1 = make_float4(l0 + bi1.x + bh1.x, h0 + bi1.y + bh1.y,
                                l1 + bi1.z + bh1.z, h1 + bi1.w + bh1.w);
        *(float4*)&crow[n1] = v1;
        unpack2(acc[i][2], l0, h0);
        unpack2(acc[i][3], l1, h1);
        float4 v2 = make_float4(l0 + bi2.x + bh2.x, h0 + bi2.y + bh2.y,
                                l1 + bi2.z + bh2.z, h1 + bi2.w + bh2.w);
        *(float4*)&crow[n2] = v2;
    }
}

// ---------------- persistent LSTM scan: payload epochs + nanosleep backoff ----------------
#define SCAN_CTAS 128

__device__ __forceinline__ float fast_sigmoid(float x) {
    return __fdividef(1.f, 1.f + __expf(-x));
}
__device__ __forceinline__ float fast_tanh(float x) {
    float e = __expf(-2.f * x);
    return __fdividef(1.f - e, 1.f + e);
}
__device__ __forceinline__ unsigned long long ld_rlx(const unsigned long long* p) {
    unsigned long long v;
    asm volatile("ld.relaxed.gpu.global.u64 %0, [%1];" : "=l"(v) : "l"(p) : "memory");
    return v;
}
__device__ __forceinline__ void st_rlx(unsigned long long* p, unsigned long long v) {
    asm volatile("st.relaxed.gpu.global.u64 [%0], %1;" :: "l"(p), "l"(v) : "memory");
}

__global__ __launch_bounds__(256, 1)
void scan_kernel(const float* __restrict__ Whh) {
    __shared__ float hs[2][HID];   // double-buffered: one barrier per step

    const int tid  = threadIdx.x;
    const int warp = tid >> 5;
    const int lane = tid & 31;
    const int b    = blockIdx.x;
    const int j    = b * 8 + warp;   // this warp's hidden unit

    // W fragment in registers: gate g, chunk i -> floats [lane*4 + i*128, +4)
    unsigned long long wreg[4][8][2];
#pragma unroll
    for (int g = 0; g < 4; g++) {
        const float* wrow = Whh + (size_t)(g * HID + j) * HID;
#pragma unroll
        for (int i = 0; i < 8; i++) {
            ulonglong2 v = *(const ulonglong2*)&wrow[lane * 4 + i * 128];
            wreg[g][i][0] = v.x;
            wreg[g][i][1] = v.y;
        }
    }

    float cstate = 0.f;

    for (int t = 0; t < T_STEPS; t++) {
        // prefetch this step's x_proj gates (independent of h)
        float xg0 = __ldg(&g_xproj[(size_t)t * GATES + 0 * HID + j]);
        float xg1 = __ldg(&g_xproj[(size_t)t * GATES + 1 * HID + j]);
        float xg2 = __ldg(&g_xproj[(size_t)t * GATES + 2 * HID + j]);
        float xg3 = __ldg(&g_xproj[(size_t)t * GATES + 3 * HID + j]);

        // ---- acquire h_t: poll our 4 payload words; nanosleep on miss so the
        //      LSU / L1tex queue drains instead of being flooded by spin LDGs ----
        const unsigned long long* p0 = g_hp[t & 1] + tid;
        const unsigned int want = (unsigned int)t;
        unsigned long long v0, v1, v2, v3;
        for (;;) {
            v0 = ld_rlx(p0);
            v1 = ld_rlx(p0 + 256);
            v2 = ld_rlx(p0 + 512);
            v3 = ld_rlx(p0 + 768);
            bool ok = ((unsigned int)(v0 >> 32) == want) &
                      ((unsigned int)(v1 >> 32) == want) &
                      ((unsigned int)(v2 >> 32) == want) &
                      ((unsigned int)(v3 >> 32) == want);
            if (ok) break;
            __nanosleep(100);
        }
        float* cur = hs[t & 1];
        cur[tid]       = __uint_as_float((unsigned int)v0);
        cur[tid + 256] = __uint_as_float((unsigned int)v1);
        cur[tid + 512] = __uint_as_float((unsigned int)v2);
        cur[tid + 768] = __uint_as_float((unsigned int)v3);
        __syncthreads();

        // ---- gate matvec (W in regs, h in smem) ----
        unsigned long long acc[4] = {0ULL, 0ULL, 0ULL, 0ULL};
#pragma unroll
        for (int i = 0; i < 8; i++) {
            ulonglong2 h2 = *(const ulonglong2*)&cur[lane * 4 + i * 128];
#pragma unroll
            for (int g = 0; g < 4; g++) {
                ffma2(acc[g], h2.x, wreg[g][i][0]);
                ffma2(acc[g], h2.y, wreg[g][i][1]);
            }
        }

        float red[4];
#pragma unroll
        for (int g = 0; g < 4; g++) {
            float lo, hi;
            unpack2(acc[g], lo, hi);
            red[g] = lo + hi;
        }
#pragma unroll
        for (int o = 16; o; o >>= 1) {
#pragma unroll
            for (int g = 0; g < 4; g++)
                red[g] += __shfl_xor_sync(0xffffffffu, red[g], o);
        }

        float gi = fast_sigmoid(xg0 + red[0]);
        float gf = fast_sigmoid(xg1 + red[1]);
        float gg = fast_tanh(xg2 + red[2]);
        float go = fast_sigmoid(xg3 + red[3]);
        cstate = gf * cstate + gi * gg;
        float hnew = go * fast_tanh(cstate);

        // ---- publish h_{t+1} = {epoch t+1 | bits} ----
        if (lane == 0) {
            unsigned long long pk =
                ((unsigned long long)(unsigned int)(t + 1) << 32) |
                (unsigned long long)__float_as_uint(hnew);
            st_rlx(&g_hp[(t + 1) & 1][j], pk);
        }
    }
}

// ---------------- final: out = h_T @ fc_w^T + fc_b ----------------
__global__ __launch_bounds__(256, 2)
void final_kernel(const float* __restrict__ fcw,
                  const float* __restrict__ fcb,
                  float* __restrict__ out) {
    __shared__ float hs[HID];
    const int tid = threadIdx.x, warp = tid >> 5, lane = tid & 31;
    // h_T (epoch 256) lives in g_hp[0]; kernel boundary guarantees visibility
#pragma unroll
    for (int q = 0; q < 4; q++)
        hs[tid + q * 256] = __uint_as_float((unsigned int)g_hp[0][tid + q * 256]);
    __syncthreads();

    int row = blockIdx.x * 16 + warp * 2;
    const float* wr0 = fcw + (size_t)row * HID;
    const float* wr1 = wr0 + HID;
    float acc0 = 0.f, acc1 = 0.f;
#pragma unroll
    for (int i = 0; i < 8; i++) {
        float4 h4 = *(const float4*)&hs[lane * 4 + i * 128];
        float4 a4 = *(const float4*)&wr0[lane * 4 + i * 128];
        float4 b4 = *(const float4*)&wr1[lane * 4 + i * 128];
        acc0 += a4.x * h4.x + a4.y * h4.y + a4.z * h4.z + a4.w * h4.w;
        acc1 += b4.x * h4.x + b4.y * h4.y + b4.z * h4.z + b4.w * h4.w;
    }
#pragma unroll
    for (int o = 16; o; o >>= 1) {
        acc0 += __shfl_xor_sync(0xffffffffu, acc0, o);
        acc1 += __shfl_xor_sync(0xffffffffu, acc1, o);
    }
    if (lane == 0) {
        out[row]     = acc0 + fcb[row];
        out[row + 1] = acc1 + fcb[row + 1];
    }
}

// ---------------- launch ----------------
extern "C" void kernel_launch(void* const* d_in, const int* in_sizes, int n_in,
                              void* d_out, int out_size) {
    const float* frames = (const float*)d_in[0];
    const float* W_ih   = (const float*)d_in[1];
    const float* W_hh   = (const float*)d_in[2];
    const float* b_ih   = (const float*)d_in[3];
    const float* b_hh   = (const float*)d_in[4];
    const float* fc_w   = (const float*)d_in[5];
    const float* fc_b   = (const float*)d_in[6];
    float* out = (float*)d_out;

    init_kernel<<<4, 256>>>();

    dim3 g1(GATES / BN, T_STEPS / BM);   // (32, 4) = 128 CTAs
    gemm1_kernel<<<g1, 256>>>(frames, W_ih, b_ih, b_hh);

    scan_kernel<<<SCAN_CTAS, 256>>>(W_hh);

    final_kernel<<<12288 / 16, 256>>>(fc_w, fc_b, out);
}

// round 10
// speedup vs baseline: 2.6383x; 1.9375x over previous
#include <cuda_runtime.h>
#include <cuda_bf16.h>
#include <cstdint>
#include <math.h>

#define T_STEPS 256
#define INPUT   12288
#define HID     1024
#define GATES   4096

// ---------------- device scratch (no allocations allowed) ----------------
__device__ float              g_xproj[T_STEPS * GATES];  // 4 MB
__device__ unsigned long long g_hp[2][HID];              // {epoch|h} ping-pong
// bf16 hi/lo split operands for the tensor-core GEMM
__device__ __nv_bfloat16 g_Ahi[T_STEPS * INPUT];
__device__ __nv_bfloat16 g_Alo[T_STEPS * INPUT];
__device__ __nv_bfloat16 g_Bhi[GATES * INPUT];
__device__ __nv_bfloat16 g_Blo[GATES * INPUT];

// ---------------- helpers: packed f32x2 FMA (scan) ----------------
__device__ __forceinline__ void ffma2(unsigned long long& d,
                                      unsigned long long a,
                                      unsigned long long b) {
    asm("fma.rn.f32x2 %0, %1, %2, %0;" : "+l"(d) : "l"(a), "l"(b));
}
__device__ __forceinline__ void unpack2(unsigned long long v, float& lo, float& hi) {
    asm("mov.b64 {%0, %1}, %2;" : "=f"(lo), "=f"(hi) : "l"(v));
}

// ---------------- init ----------------
__global__ void init_kernel() {
    int tid = blockIdx.x * blockDim.x + threadIdx.x;
    if (tid < HID) {
        g_hp[0][tid] = 0ULL;
        g_hp[1][tid] = 0ULL;
    }
}

// ---------------- split: fp32 -> bf16 hi + bf16 lo ----------------
__device__ __forceinline__ void split1(float x, float& hi, float& lo) {
    __nv_bfloat16 h = __float2bfloat16_rn(x);
    hi = __bfloat162float(h);
    lo = x - hi;
}
__device__ __forceinline__ unsigned int pack2f(float a, float b) {
    __nv_bfloat162 t = __floats2bfloat162_rn(a, b);
    return *reinterpret_cast<unsigned int*>(&t);
}
__global__ __launch_bounds__(256)
void split_kernel(const float* __restrict__ A, const float* __restrict__ W) {
    const int NB = GATES * INPUT / 4;
    const int NA = T_STEPS * INPUT / 4;
    int stride = gridDim.x * blockDim.x;
    for (int i = blockIdx.x * blockDim.x + threadIdx.x; i < NB + NA; i += stride) {
        const float4* src; uint2* dhi; uint2* dlo; int k;
        if (i < NB) { src = (const float4*)W; dhi = (uint2*)g_Bhi; dlo = (uint2*)g_Blo; k = i; }
        else        { src = (const float4*)A; dhi = (uint2*)g_Ahi; dlo = (uint2*)g_Alo; k = i - NB; }
        float4 v = src[k];
        float h0, h1, h2, h3, l0, l1, l2, l3;
        split1(v.x, h0, l0); split1(v.y, h1, l1);
        split1(v.z, h2, l2); split1(v.w, h3, l3);
        uint2 hi, lo;
        hi.x = pack2f(h0, h1); hi.y = pack2f(h2, h3);
        lo.x = pack2f(l0, l1); lo.y = pack2f(l2, l3);
        dhi[k] = hi; dlo[k] = lo;
    }
}

// ---------------- mma.sync GEMM: x_proj = frames @ W_ih^T + biases ----------------
// CTA tile 128m x 64n, 8 warps as 4(m) x 2(n), warp tile 32x32.
// Fragments loaded directly (m16n8k16 layout maps to contiguous bf16 pairs).
#define GK 32
#define NCH (INPUT / GK)        // 384 chunks
#define ROWPAD 40               // bf16 per smem row (80 B) -> conflict-free frags
#define A_MAT_B (128 * ROWPAD * 2)   // 10240 B per A matrix per stage
#define B_MAT_B (64 * ROWPAD * 2)    //  5120 B per B matrix per stage
#define STAGE_B (2 * A_MAT_B + 2 * B_MAT_B)   // 30720
#define GEMM_SMEM (2 * STAGE_B)               // 61440
#define OFF_AH 0
#define OFF_AL A_MAT_B
#define OFF_BH (2 * A_MAT_B)
#define OFF_BL (2 * A_MAT_B + B_MAT_B)

__device__ __forceinline__ void mma_bf16(float c[4], const uint32_t a[4],
                                         const uint32_t b[2]) {
    asm volatile(
        "mma.sync.aligned.m16n8k16.row.col.f32.bf16.bf16.f32 "
        "{%0,%1,%2,%3}, {%4,%5,%6,%7}, {%8,%9}, {%0,%1,%2,%3};"
        : "+f"(c[0]), "+f"(c[1]), "+f"(c[2]), "+f"(c[3])
        : "r"(a[0]), "r"(a[1]), "r"(a[2]), "r"(a[3]), "r"(b[0]), "r"(b[1]));
}

__global__ __launch_bounds__(256, 1)
void gemm_mma_kernel(const float* __restrict__ b_ih, const float* __restrict__ b_hh) {
    extern __shared__ char smem[];
    const int tid  = threadIdx.x;
    const int warp = tid >> 5;
    const int lane = tid & 31;
    const int g    = lane >> 2;      // group id (0..7)
    const int tg   = lane & 3;       // thread in group
    const int n0   = blockIdx.x * 64;
    const int m0   = blockIdx.y * 128;
    const int wm   = (warp & 3) * 32;   // warp m offset in tile
    const int wn   = (warp >> 2) * 32;  // warp n offset in tile

    float acc[2][4][4];
#pragma unroll
    for (int i = 0; i < 2; i++)
#pragma unroll
        for (int j = 0; j < 4; j++)
#pragma unroll
            for (int q = 0; q < 4; q++) acc[i][j][q] = 0.f;

    // global-load index mapping (fixed per thread)
    // A: 512 uint4 per matrix per chunk -> 2 per thread; B: 256 -> 1 per thread
    int rA[2], cA[2];
#pragma unroll
    for (int p = 0; p < 2; p++) { int idx = tid + p * 256; rA[p] = idx >> 2; cA[p] = idx & 3; }
    const int rB = tid >> 2, cB = tid & 3;

    uint4 pAh[2], pAl[2], pBh, pBl;

    // prologue: LDG chunk 0
#pragma unroll
    for (int p = 0; p < 2; p++) {
        size_t off = (size_t)(m0 + rA[p]) * INPUT + cA[p] * 8;
        pAh[p] = *(const uint4*)(g_Ahi + off);
        pAl[p] = *(const uint4*)(g_Alo + off);
    }
    {
        size_t off = (size_t)(n0 + rB) * INPUT + cB * 8;
        pBh = *(const uint4*)(g_Bhi + off);
        pBl = *(const uint4*)(g_Blo + off);
    }
    // STS chunk 0 -> stage 0
    {
        char* st = smem;
#pragma unroll
        for (int p = 0; p < 2; p++) {
            uint32_t d = rA[p] * 80 + cA[p] * 16;
            *(uint4*)(st + OFF_AH + d) = pAh[p];
            *(uint4*)(st + OFF_AL + d) = pAl[p];
        }
        uint32_t d = rB * 80 + cB * 16;
        *(uint4*)(st + OFF_BH + d) = pBh;
        *(uint4*)(st + OFF_BL + d) = pBl;
    }
    __syncthreads();

    int buf = 0;
    for (int c = 0; c < NCH; c++) {
        if (c + 1 < NCH) {
            int kb = (c + 1) * GK;
#pragma unroll
            for (int p = 0; p < 2; p++) {
                size_t off = (size_t)(m0 + rA[p]) * INPUT + kb + cA[p] * 8;
                pAh[p] = *(const uint4*)(g_Ahi + off);
                pAl[p] = *(const uint4*)(g_Alo + off);
            }
            size_t off = (size_t)(n0 + rB) * INPUT + kb + cB * 8;
            pBh = *(const uint4*)(g_Bhi + off);
            pBl = *(const uint4*)(g_Blo + off);
        }

        // ---- compute on stage buf: 2 k16 steps ----
        const char* st = smem + buf * STAGE_B;
#pragma unroll
        for (int kk = 0; kk < 2; kk++) {
            const int kbyte = kk * 32 + tg * 4;   // (tg*2 + kk*16) bf16 -> bytes
            uint32_t ah[2][4], al[2][4], bh[4][2], bl[4][2];
#pragma unroll
            for (int am = 0; am < 2; am++) {
                uint32_t r0 = (wm + am * 16 + g) * 80 + kbyte;
                uint32_t r1 = r0 + 8 * 80;
                ah[am][0] = *(const uint32_t*)(st + OFF_AH + r0);
                ah[am][1] = *(const uint32_t*)(st + OFF_AH + r1);
                ah[am][2] = *(const uint32_t*)(st + OFF_AH + r0 + 16);
                ah[am][3] = *(const uint32_t*)(st + OFF_AH + r1 + 16);
                al[am][0] = *(const uint32_t*)(st + OFF_AL + r0);
                al[am][1] = *(const uint32_t*)(st + OFF_AL + r1);
                al[am][2] = *(const uint32_t*)(st + OFF_AL + r0 + 16);
                al[am][3] = *(const uint32_t*)(st + OFF_AL + r1 + 16);
            }
#pragma unroll
            for (int an = 0; an < 4; an++) {
                uint32_t rb = (wn + an * 8 + g) * 80 + kbyte;
                bh[an][0] = *(const uint32_t*)(st + OFF_BH + rb);
                bh[an][1] = *(const uint32_t*)(st + OFF_BH + rb + 16);
                bl[an][0] = *(const uint32_t*)(st + OFF_BL + rb);
                bl[an][1] = *(const uint32_t*)(st + OFF_BL + rb + 16);
            }
#pragma unroll
            for (int am = 0; am < 2; am++)
#pragma unroll
                for (int an = 0; an < 4; an++) {
                    mma_bf16(acc[am][an], ah[am], bh[an]);
                    mma_bf16(acc[am][an], ah[am], bl[an]);
                    mma_bf16(acc[am][an], al[am], bh[an]);
                }
        }

        // ---- STS next chunk into other stage ----
        if (c + 1 < NCH) {
            char* sn = smem + (buf ^ 1) * STAGE_B;
#pragma unroll
            for (int p = 0; p < 2; p++) {
                uint32_t d = rA[p] * 80 + cA[p] * 16;
                *(uint4*)(sn + OFF_AH + d) = pAh[p];
                *(uint4*)(sn + OFF_AL + d) = pAl[p];
            }
            uint32_t d = rB * 80 + cB * 16;
            *(uint4*)(sn + OFF_BH + d) = pBh;
            *(uint4*)(sn + OFF_BL + d) = pBl;
            __syncthreads();
            buf ^= 1;
        }
    }

    // ---- epilogue: add biases, store ----
#pragma unroll
    for (int am = 0; am < 2; am++) {
        int m = m0 + wm + am * 16 + g;
#pragma unroll
        for (int an = 0; an < 4; an++) {
            int n = n0 + wn + an * 8 + tg * 2;
            float bi0 = b_ih[n]     + b_hh[n];
            float bi1 = b_ih[n + 1] + b_hh[n + 1];
            float2 v0 = make_float2(acc[am][an][0] + bi0, acc[am][an][1] + bi1);
            float2 v1 = make_float2(acc[am][an][2] + bi0, acc[am][an][3] + bi1);
            *(float2*)&g_xproj[(size_t)m * GATES + n]       = v0;
            *(float2*)&g_xproj[(size_t)(m + 8) * GATES + n] = v1;
        }
    }
}

// ---------------- persistent LSTM scan: R5 verbatim ----------------
#define SCAN_CTAS 128

__device__ __forceinline__ float fast_sigmoid(float x) {
    return __fdividef(1.f, 1.f + __expf(-x));
}
__device__ __forceinline__ float fast_tanh(float x) {
    float e = __expf(-2.f * x);
    return __fdividef(1.f - e, 1.f + e);
}
__device__ __forceinline__ unsigned long long ld_rlx(const unsigned long long* p) {
    unsigned long long v;
    asm volatile("ld.relaxed.gpu.global.u64 %0, [%1];" : "=l"(v) : "l"(p) : "memory");
    return v;
}
__device__ __forceinline__ void st_rlx(unsigned long long* p, unsigned long long v) {
    asm volatile("st.relaxed.gpu.global.u64 [%0], %1;" :: "l"(p), "l"(v) : "memory");
}

__global__ __launch_bounds__(256, 1)
void scan_kernel(const float* __restrict__ Whh) {
    __shared__ float hs[2][HID];

    const int tid  = threadIdx.x;
    const int warp = tid >> 5;
    const int lane = tid & 31;
    const int b    = blockIdx.x;
    const int j    = b * 8 + warp;

    unsigned long long wreg[4][8][2];
#pragma unroll
    for (int g = 0; g < 4; g++) {
        const float* wrow = Whh + (size_t)(g * HID + j) * HID;
#pragma unroll
        for (int i = 0; i < 8; i++) {
            ulonglong2 v = *(const ulonglong2*)&wrow[lane * 4 + i * 128];
            wreg[g][i][0] = v.x;
            wreg[g][i][1] = v.y;
        }
    }

    float cstate = 0.f;

    for (int t = 0; t < T_STEPS; t++) {
        float xg0 = __ldg(&g_xproj[(size_t)t * GATES + 0 * HID + j]);
        float xg1 = __ldg(&g_xproj[(size_t)t * GATES + 1 * HID + j]);
        float xg2 = __ldg(&g_xproj[(size_t)t * GATES + 2 * HID + j]);
        float xg3 = __ldg(&g_xproj[(size_t)t * GATES + 3 * HID + j]);

        const unsigned long long* p0 = g_hp[t & 1] + tid;
        const unsigned int want = (unsigned int)t;
        unsigned long long v0, v1, v2, v3;
        bool ok;
        do {
            v0 = ld_rlx(p0);
            v1 = ld_rlx(p0 + 256);
            v2 = ld_rlx(p0 + 512);
            v3 = ld_rlx(p0 + 768);
            ok = ((unsigned int)(v0 >> 32) == want) &
                 ((unsigned int)(v1 >> 32) == want) &
                 ((unsigned int)(v2 >> 32) == want) &
                 ((unsigned int)(v3 >> 32) == want);
        } while (!ok);
        float* cur = hs[t & 1];
        cur[tid]       = __uint_as_float((unsigned int)v0);
        cur[tid + 256] = __uint_as_float((unsigned int)v1);
        cur[tid + 512] = __uint_as_float((unsigned int)v2);
        cur[tid + 768] = __uint_as_float((unsigned int)v3);
        __syncthreads();

        unsigned long long acc[4] = {0ULL, 0ULL, 0ULL, 0ULL};
#pragma unroll
        for (int i = 0; i < 8; i++) {
            ulonglong2 h2 = *(const ulonglong2*)&cur[lane * 4 + i * 128];
#pragma unroll
            for (int g = 0; g < 4; g++) {
                ffma2(acc[g], h2.x, wreg[g][i][0]);
                ffma2(acc[g], h2.y, wreg[g][i][1]);
            }
        }

        float red[4];
#pragma unroll
        for (int g = 0; g < 4; g++) {
            float lo, hi;
            unpack2(acc[g], lo, hi);
            red[g] = lo + hi;
        }
#pragma unroll
        for (int o = 16; o; o >>= 1) {
#pragma unroll
            for (int g = 0; g < 4; g++)
                red[g] += __shfl_xor_sync(0xffffffffu, red[g], o);
        }

        float gi = fast_sigmoid(xg0 + red[0]);
        float gf = fast_sigmoid(xg1 + red[1]);
        float gg = fast_tanh(xg2 + red[2]);
        float go = fast_sigmoid(xg3 + red[3]);
        cstate = gf * cstate + gi * gg;
        float hnew = go * fast_tanh(cstate);

        if (lane == 0) {
            unsigned long long pk =
                ((unsigned long long)(unsigned int)(t + 1) << 32) |
                (unsigned long long)__float_as_uint(hnew);
            st_rlx(&g_hp[(t + 1) & 1][j], pk);
        }
    }
}

// ---------------- final: out = h_T @ fc_w^T + fc_b ----------------
__global__ __launch_bounds__(256, 2)
void final_kernel(const float* __restrict__ fcw,
                  const float* __restrict__ fcb,
                  float* __restrict__ out) {
    __shared__ float hs[HID];
    const int tid = threadIdx.x, warp = tid >> 5, lane = tid & 31;
#pragma unroll
    for (int q = 0; q < 4; q++)
        hs[tid + q * 256] = __uint_as_float((unsigned int)g_hp[0][tid + q * 256]);
    __syncthreads();

    int row = blockIdx.x * 16 + warp * 2;
    const float* wr0 = fcw + (size_t)row * HID;
    const float* wr1 = wr0 + HID;
    float acc0 = 0.f, acc1 = 0.f;
#pragma unroll
    for (int i = 0; i < 8; i++) {
        float4 h4 = *(const float4*)&hs[lane * 4 + i * 128];
        float4 a4 = *(const float4*)&wr0[lane * 4 + i * 128];
        float4 b4 = *(const float4*)&wr1[lane * 4 + i * 128];
        acc0 += a4.x * h4.x + a4.y * h4.y + a4.z * h4.z + a4.w * h4.w;
        acc1 += b4.x * h4.x + b4.y * h4.y + b4.z * h4.z + b4.w * h4.w;
    }
#pragma unroll
    for (int o = 16; o; o >>= 1) {
        acc0 += __shfl_xor_sync(0xffffffffu, acc0, o);
        acc1 += __shfl_xor_sync(0xffffffffu, acc1, o);
    }
    if (lane == 0) {
        out[row]     = acc0 + fcb[row];
        out[row + 1] = acc1 + fcb[row + 1];
    }
}

// ---------------- launch ----------------
extern "C" void kernel_launch(void* const* d_in, const int* in_sizes, int n_in,
                              void* d_out, int out_size) {
    const float* frames = (const float*)d_in[0];
    const float* W_ih   = (const float*)d_in[1];
    const float* W_hh   = (const float*)d_in[2];
    const float* b_ih   = (const float*)d_in[3];
    const float* b_hh   = (const float*)d_in[4];
    const float* fc_w   = (const float*)d_in[5];
    const float* fc_b   = (const float*)d_in[6];
    float* out = (float*)d_out;

    cudaFuncSetAttribute(gemm_mma_kernel,
                         cudaFuncAttributeMaxDynamicSharedMemorySize, GEMM_SMEM);

    init_kernel<<<4, 256>>>();

    split_kernel<<<2048, 256>>>(frames, W_ih);

    dim3 gg(GATES / 64, T_STEPS / 128);   // (64, 2) = 128 CTAs
    gemm_mma_kernel<<<gg, 256, GEMM_SMEM>>>(b_ih, b_hh);

    scan_kernel<<<SCAN_CTAS, 256>>>(W_hh);

    final_kernel<<<12288 / 16, 256>>>(fc_w, fc_b, out);
}

// round 11
// speedup vs baseline: 2.7427x; 1.0396x over previous
#include <cuda_runtime.h>
#include <cuda_bf16.h>
#include <cstdint>
#include <math.h>

#define T_STEPS 256
#define INPUT   12288
#define HID     1024
#define GATES   4096

// ---------------- device scratch (no allocations allowed) ----------------
__device__ float              g_xproj[T_STEPS * GATES];  // 4 MB
__device__ unsigned long long g_hp[2][HID];              // {epoch|h} ping-pong
// bf16 hi/lo split of A (frames) only — W is converted inside the GEMM
__device__ __nv_bfloat16 g_Ahi[T_STEPS * INPUT];
__device__ __nv_bfloat16 g_Alo[T_STEPS * INPUT];

// ---------------- helpers: packed f32x2 FMA (scan) ----------------
__device__ __forceinline__ void ffma2(unsigned long long& d,
                                      unsigned long long a,
                                      unsigned long long b) {
    asm("fma.rn.f32x2 %0, %1, %2, %0;" : "+l"(d) : "l"(a), "l"(b));
}
__device__ __forceinline__ void unpack2(unsigned long long v, float& lo, float& hi) {
    asm("mov.b64 {%0, %1}, %2;" : "=f"(lo), "=f"(hi) : "l"(v));
}

// ---------------- init ----------------
__global__ void init_kernel() {
    int tid = blockIdx.x * blockDim.x + threadIdx.x;
    if (tid < HID) {
        g_hp[0][tid] = 0ULL;
        g_hp[1][tid] = 0ULL;
    }
}

// ---------------- split A only: fp32 -> bf16 hi + lo ----------------
__device__ __forceinline__ unsigned int pack2f(float a, float b) {
    __nv_bfloat162 t = __floats2bfloat162_rn(a, b);
    return *reinterpret_cast<unsigned int*>(&t);
}
// convert float pair -> (hi bf16x2, lo bf16x2)
__device__ __forceinline__ void cvt_pair(float f0, float f1,
                                         unsigned int& h01, unsigned int& l01) {
    h01 = pack2f(f0, f1);
    float h0 = __uint_as_float(h01 << 16);
    float h1 = __uint_as_float(h01 & 0xFFFF0000u);
    l01 = pack2f(f0 - h0, f1 - h1);
}
__global__ __launch_bounds__(256)
void splitA_kernel(const float* __restrict__ A) {
    const int NA = T_STEPS * INPUT / 4;
    int stride = gridDim.x * blockDim.x;
    for (int i = blockIdx.x * blockDim.x + threadIdx.x; i < NA; i += stride) {
        float4 v = ((const float4*)A)[i];
        uint2 hi, lo;
        cvt_pair(v.x, v.y, hi.x, lo.x);
        cvt_pair(v.z, v.w, hi.y, lo.y);
        ((uint2*)g_Ahi)[i] = hi;
        ((uint2*)g_Alo)[i] = lo;
    }
}

// ---------------- fused mma.sync GEMM ----------------
// x_proj = frames @ W_ih^T + b_ih + b_hh.  CTA tile 128m x 64n, grid (64, 2).
// A read pre-split bf16; W read fp32 and converted to hi/lo in-kernel.
// Fragments via ldmatrix.x4.  3 bf16 products per k16 (hh + hl + lh).
#define GK 32
#define NCH (INPUT / GK)        // 384 chunks
#define A_MAT_B (128 * 80)      // 10240 B (128 rows x 80B padded)
#define B_MAT_B (64 * 80)       //  5120 B
#define STAGE_B (2 * A_MAT_B + 2 * B_MAT_B)   // 30720
#define GEMM_SMEM (2 * STAGE_B)               // 61440
#define OFF_AH 0
#define OFF_AL A_MAT_B
#define OFF_BH (2 * A_MAT_B)
#define OFF_BL (2 * A_MAT_B + B_MAT_B)

__device__ __forceinline__ uint32_t smem_u32(const void* p) {
    uint32_t a;
    asm("{ .reg .u64 t; cvta.to.shared.u64 t, %1; cvt.u32.u64 %0, t; }" : "=r"(a) : "l"(p));
    return a;
}
__device__ __forceinline__ void lm4(uint32_t& d0, uint32_t& d1, uint32_t& d2,
                                    uint32_t& d3, uint32_t addr) {
    asm volatile("ldmatrix.sync.aligned.m8n8.x4.shared.b16 {%0,%1,%2,%3}, [%4];"
                 : "=r"(d0), "=r"(d1), "=r"(d2), "=r"(d3) : "r"(addr));
}
__device__ __forceinline__ void mma_bf16(float c[4], const uint32_t a[4],
                                         const uint32_t b[2]) {
    asm volatile(
        "mma.sync.aligned.m16n8k16.row.col.f32.bf16.bf16.f32 "
        "{%0,%1,%2,%3}, {%4,%5,%6,%7}, {%8,%9}, {%0,%1,%2,%3};"
        : "+f"(c[0]), "+f"(c[1]), "+f"(c[2]), "+f"(c[3])
        : "r"(a[0]), "r"(a[1]), "r"(a[2]), "r"(a[3]), "r"(b[0]), "r"(b[1]));
}

__global__ __launch_bounds__(256, 1)
void gemm_fused_kernel(const float* __restrict__ W,
                       const float* __restrict__ b_ih,
                       const float* __restrict__ b_hh) {
    extern __shared__ char smem[];
    const uint32_t sbase = smem_u32(smem);
    const int tid  = threadIdx.x;
    const int warp = tid >> 5;
    const int lane = tid & 31;
    const int g    = lane >> 2;
    const int tg   = lane & 3;
    const int n0   = blockIdx.x * 64;
    const int m0   = blockIdx.y * 128;
    const int wm   = (warp & 3) * 32;
    const int wn   = (warp >> 2) * 32;

    float acc[2][4][4];
#pragma unroll
    for (int i = 0; i < 2; i++)
#pragma unroll
        for (int j = 0; j < 4; j++)
#pragma unroll
            for (int q = 0; q < 4; q++) acc[i][j][q] = 0.f;

    // ldmatrix per-lane offsets (bytes within a matrix region)
    // A 16x16 block: mats = [r0-7/klo, r8-15/klo, r0-7/khi, r8-15/khi]
    const uint32_t aOff = (uint32_t)((wm + ((lane >> 3) & 1) * 8 + (lane & 7)) * 80
                                     + (lane >> 4) * 16);
    // B x4 covers 2 n-blocks: mats = [n0-7/klo, n0-7/khi, n8-15/klo, n8-15/khi]
    const uint32_t bOff = (uint32_t)((wn + (lane >> 4) * 8 + (lane & 7)) * 80
                                     + ((lane >> 3) & 1) * 16);

    // global-load mappings (fixed per thread)
    // A bf16: 512 uint4 per matrix per chunk -> 2/thread; row = idx>>2, c16 = idx&3
    int arow[2], ac[2];
#pragma unroll
    for (int p = 0; p < 2; p++) { int idx = tid + p * 256; arow[p] = idx >> 2; ac[p] = idx & 3; }
    // W fp32: 512 float4 per chunk -> 2/thread; row = idx>>3, c4 = idx&7
    int brow[2], bc[2];
#pragma unroll
    for (int p = 0; p < 2; p++) { int idx = tid + p * 256; brow[p] = idx >> 3; bc[p] = idx & 7; }

    uint4 pAh[2], pAl[2];
    float4 pW[2];

    // ---- prologue: LDG chunk 0, convert, STS -> stage 0 ----
#pragma unroll
    for (int p = 0; p < 2; p++) {
        size_t off = (size_t)(m0 + arow[p]) * INPUT + ac[p] * 8;
        pAh[p] = *(const uint4*)(g_Ahi + off);
        pAl[p] = *(const uint4*)(g_Alo + off);
        pW[p]  = *(const float4*)(W + (size_t)(n0 + brow[p]) * INPUT + bc[p] * 4);
    }
    {
        char* st = smem;
#pragma unroll
        for (int p = 0; p < 2; p++) {
            uint32_t d = arow[p] * 80 + ac[p] * 16;
            *(uint4*)(st + OFF_AH + d) = pAh[p];
            *(uint4*)(st + OFF_AL + d) = pAl[p];
            uint2 h, l;
            cvt_pair(pW[p].x, pW[p].y, h.x, l.x);
            cvt_pair(pW[p].z, pW[p].w, h.y, l.y);
            uint32_t e = brow[p] * 80 + bc[p] * 8;
            *(uint2*)(st + OFF_BH + e) = h;
            *(uint2*)(st + OFF_BL + e) = l;
        }
    }
    __syncthreads();

    int buf = 0;
    for (int c = 0; c < NCH; c++) {
        if (c + 1 < NCH) {
            int kb = (c + 1) * GK;
#pragma unroll
            for (int p = 0; p < 2; p++) {
                size_t off = (size_t)(m0 + arow[p]) * INPUT + kb + ac[p] * 8;
                pAh[p] = *(const uint4*)(g_Ahi + off);
                pAl[p] = *(const uint4*)(g_Alo + off);
                pW[p]  = *(const float4*)(W + (size_t)(n0 + brow[p]) * INPUT + kb + bc[p] * 4);
            }
        }

        // ---- compute on stage buf ----
        const uint32_t st = sbase + buf * STAGE_B;
#pragma unroll
        for (int kk = 0; kk < 2; kk++) {
            const uint32_t kb = kk * 32;
            uint32_t ah[2][4], al[2][4], bh[8], bl[8];
#pragma unroll
            for (int am = 0; am < 2; am++) {
                lm4(ah[am][0], ah[am][1], ah[am][2], ah[am][3],
                    st + OFF_AH + aOff + am * 1280 + kb);
                lm4(al[am][0], al[am][1], al[am][2], al[am][3],
                    st + OFF_AL + aOff + am * 1280 + kb);
            }
            // bh: [an0.b0, an0.b1, an1.b0, an1.b1] then an2/an3
            lm4(bh[0], bh[1], bh[2], bh[3], st + OFF_BH + bOff + kb);
            lm4(bh[4], bh[5], bh[6], bh[7], st + OFF_BH + bOff + 1280 + kb);
            lm4(bl[0], bl[1], bl[2], bl[3], st + OFF_BL + bOff + kb);
            lm4(bl[4], bl[5], bl[6], bl[7], st + OFF_BL + bOff + 1280 + kb);
#pragma unroll
            for (int am = 0; am < 2; am++)
#pragma unroll
                for (int an = 0; an < 4; an++) {
                    mma_bf16(acc[am][an], ah[am], &bh[an * 2]);
                    mma_bf16(acc[am][an], ah[am], &bl[an * 2]);
                    mma_bf16(acc[am][an], al[am], &bh[an * 2]);
                }
        }

        // ---- convert + STS next chunk into other stage ----
        if (c + 1 < NCH) {
            char* sn = smem + (buf ^ 1) * STAGE_B;
#pragma unroll
            for (int p = 0; p < 2; p++) {
                uint32_t d = arow[p] * 80 + ac[p] * 16;
                *(uint4*)(sn + OFF_AH + d) = pAh[p];
                *(uint4*)(sn + OFF_AL + d) = pAl[p];
                uint2 h, l;
                cvt_pair(pW[p].x, pW[p].y, h.x, l.x);
                cvt_pair(pW[p].z, pW[p].w, h.y, l.y);
                uint32_t e = brow[p] * 80 + bc[p] * 8;
                *(uint2*)(sn + OFF_BH + e) = h;
                *(uint2*)(sn + OFF_BL + e) = l;
            }
            __syncthreads();
            buf ^= 1;
        }
    }

    // ---- epilogue: add biases, store (layout identical to R10, validated) ----
#pragma unroll
    for (int am = 0; am < 2; am++) {
        int m = m0 + wm + am * 16 + g;
#pragma unroll
        for (int an = 0; an < 4; an++) {
            int n = n0 + wn + an * 8 + tg * 2;
            float bi0 = b_ih[n]     + b_hh[n];
            float bi1 = b_ih[n + 1] + b_hh[n + 1];
            float2 v0 = make_float2(acc[am][an][0] + bi0, acc[am][an][1] + bi1);
            float2 v1 = make_float2(acc[am][an][2] + bi0, acc[am][an][3] + bi1);
            *(float2*)&g_xproj[(size_t)m * GATES + n]       = v0;
            *(float2*)&g_xproj[(size_t)(m + 8) * GATES + n] = v1;
        }
    }
}

// ---------------- persistent LSTM scan: R5 verbatim ----------------
#define SCAN_CTAS 128

__device__ __forceinline__ float fast_sigmoid(float x) {
    return __fdividef(1.f, 1.f + __expf(-x));
}
__device__ __forceinline__ float fast_tanh(float x) {
    float e = __expf(-2.f * x);
    return __fdividef(1.f - e, 1.f + e);
}
__device__ __forceinline__ unsigned long long ld_rlx(const unsigned long long* p) {
    unsigned long long v;
    asm volatile("ld.relaxed.gpu.global.u64 %0, [%1];" : "=l"(v) : "l"(p) : "memory");
    return v;
}
__device__ __forceinline__ void st_rlx(unsigned long long* p, unsigned long long v) {
    asm volatile("st.relaxed.gpu.global.u64 [%0], %1;" :: "l"(p), "l"(v) : "memory");
}

__global__ __launch_bounds__(256, 1)
void scan_kernel(const float* __restrict__ Whh) {
    __shared__ float hs[2][HID];

    const int tid  = threadIdx.x;
    const int warp = tid >> 5;
    const int lane = tid & 31;
    const int b    = blockIdx.x;
    const int j    = b * 8 + warp;

    unsigned long long wreg[4][8][2];
#pragma unroll
    for (int g = 0; g < 4; g++) {
        const float* wrow = Whh + (size_t)(g * HID + j) * HID;
#pragma unroll
        for (int i = 0; i < 8; i++) {
            ulonglong2 v = *(const ulonglong2*)&wrow[lane * 4 + i * 128];
            wreg[g][i][0] = v.x;
            wreg[g][i][1] = v.y;
        }
    }

    float cstate = 0.f;

    for (int t = 0; t < T_STEPS; t++) {
        float xg0 = __ldg(&g_xproj[(size_t)t * GATES + 0 * HID + j]);
        float xg1 = __ldg(&g_xproj[(size_t)t * GATES + 1 * HID + j]);
        float xg2 = __ldg(&g_xproj[(size_t)t * GATES + 2 * HID + j]);
        float xg3 = __ldg(&g_xproj[(size_t)t * GATES + 3 * HID + j]);

        const unsigned long long* p0 = g_hp[t & 1] + tid;
        const unsigned int want = (unsigned int)t;
        unsigned long long v0, v1, v2, v3;
        bool ok;
        do {
            v0 = ld_rlx(p0);
            v1 = ld_rlx(p0 + 256);
            v2 = ld_rlx(p0 + 512);
            v3 = ld_rlx(p0 + 768);
            ok = ((unsigned int)(v0 >> 32) == want) &
                 ((unsigned int)(v1 >> 32) == want) &
                 ((unsigned int)(v2 >> 32) == want) &
                 ((unsigned int)(v3 >> 32) == want);
        } while (!ok);
        float* cur = hs[t & 1];
        cur[tid]       = __uint_as_float((unsigned int)v0);
        cur[tid + 256] = __uint_as_float((unsigned int)v1);
        cur[tid + 512] = __uint_as_float((unsigned int)v2);
        cur[tid + 768] = __uint_as_float((unsigned int)v3);
        __syncthreads();

        unsigned long long acc[4] = {0ULL, 0ULL, 0ULL, 0ULL};
#pragma unroll
        for (int i = 0; i < 8; i++) {
            ulonglong2 h2 = *(const ulonglong2*)&cur[lane * 4 + i * 128];
#pragma unroll
            for (int g = 0; g < 4; g++) {
                ffma2(acc[g], h2.x, wreg[g][i][0]);
                ffma2(acc[g], h2.y, wreg[g][i][1]);
            }
        }

        float red[4];
#pragma unroll
        for (int g = 0; g < 4; g++) {
            float lo, hi;
            unpack2(acc[g], lo, hi);
            red[g] = lo + hi;
        }
#pragma unroll
        for (int o = 16; o; o >>= 1) {
#pragma unroll
            for (int g = 0; g < 4; g++)
                red[g] += __shfl_xor_sync(0xffffffffu, red[g], o);
        }

        float gi = fast_sigmoid(xg0 + red[0]);
        float gf = fast_sigmoid(xg1 + red[1]);
        float gg = fast_tanh(xg2 + red[2]);
        float go = fast_sigmoid(xg3 + red[3]);
        cstate = gf * cstate + gi * gg;
        float hnew = go * fast_tanh(cstate);

        if (lane == 0) {
            unsigned long long pk =
                ((unsigned long long)(unsigned int)(t + 1) << 32) |
                (unsigned long long)__float_as_uint(hnew);
            st_rlx(&g_hp[(t + 1) & 1][j], pk);
        }
    }
}

// ---------------- final: out = h_T @ fc_w^T + fc_b ----------------
__global__ __launch_bounds__(256, 2)
void final_kernel(const float* __restrict__ fcw,
                  const float* __restrict__ fcb,
                  float* __restrict__ out) {
    __shared__ float hs[HID];
    const int tid = threadIdx.x, warp = tid >> 5, lane = tid & 31;
#pragma unroll
    for (int q = 0; q < 4; q++)
        hs[tid + q * 256] = __uint_as_float((unsigned int)g_hp[0][tid + q * 256]);
    __syncthreads();

    int row = blockIdx.x * 16 + warp * 2;
    const float* wr0 = fcw + (size_t)row * HID;
    const float* wr1 = wr0 + HID;
    float acc0 = 0.f, acc1 = 0.f;
#pragma unroll
    for (int i = 0; i < 8; i++) {
        float4 h4 = *(const float4*)&hs[lane * 4 + i * 128];
        float4 a4 = *(const float4*)&wr0[lane * 4 + i * 128];
        float4 b4 = *(const float4*)&wr1[lane * 4 + i * 128];
        acc0 += a4.x * h4.x + a4.y * h4.y + a4.z * h4.z + a4.w * h4.w;
        acc1 += b4.x * h4.x + b4.y * h4.y + b4.z * h4.z + b4.w * h4.w;
    }
#pragma unroll
    for (int o = 16; o; o >>= 1) {
        acc0 += __shfl_xor_sync(0xffffffffu, acc0, o);
        acc1 += __shfl_xor_sync(0xffffffffu, acc1, o);
    }
    if (lane == 0) {
        out[row]     = acc0 + fcb[row];
        out[row + 1] = acc1 + fcb[row + 1];
    }
}

// ---------------- launch ----------------
extern "C" void kernel_launch(void* const* d_in, const int* in_sizes, int n_in,
                              void* d_out, int out_size) {
    const float* frames = (const float*)d_in[0];
    const float* W_ih   = (const float*)d_in[1];
    const float* W_hh   = (const float*)d_in[2];
    const float* b_ih   = (const float*)d_in[3];
    const float* b_hh   = (const float*)d_in[4];
    const float* fc_w   = (const float*)d_in[5];
    const float* fc_b   = (const float*)d_in[6];
    float* out = (float*)d_out;

    cudaFuncSetAttribute(gemm_fused_kernel,
                         cudaFuncAttributeMaxDynamicSharedMemorySize, GEMM_SMEM);

    init_kernel<<<4, 256>>>();

    splitA_kernel<<<1024, 256>>>(frames);

    dim3 gg(GATES / 64, T_STEPS / 128);   // (64, 2) = 128 CTAs
    gemm_fused_kernel<<<gg, 256, GEMM_SMEM>>>(W_ih, b_ih, b_hh);

    scan_kernel<<<SCAN_CTAS, 256>>>(W_hh);

    final_kernel<<<12288 / 16, 256>>>(fc_w, fc_b, out);
}